// round 13
// baseline (speedup 1.0000x reference)
#include <cuda_runtime.h>
#include <cuda_bf16.h>
#include <cstdint>

#define NN 100000
#define EE 1600000
#define D  128
#define CAP 128

// ---------------- device scratch (no allocations allowed) ----------------
__device__ int   g_cnt[NN];
__device__ int   g_colp[(size_t)NN * CAP];
// interleaved hi/lo bf16: per node 32 lane-groups of 16B = [hi01 hi23 lo01 lo23]
__device__ uint2 g_Xp[(size_t)NN * 64];
__device__ uint2 g_hp[(size_t)NN * 64];
// W transposed+split: [j=0..127][k=0..255] bf16, k<128 -> Wself[k][j], k>=128 -> Wneigh[k-128][j]
__device__ uint16_t g_WT1h[128 * 256];
__device__ uint16_t g_WT1l[128 * 256];
__device__ uint16_t g_WT2h[128 * 256];
__device__ uint16_t g_WT2l[128 * 256];

__device__ __forceinline__ uint16_t bf_hi(float v) {
    return __bfloat16_as_ushort(__float2bfloat16(v));
}
__device__ __forceinline__ float bf_f(uint32_t u) {
    return __uint_as_float(u << 16);
}

// ---------------- fused init: zero counters + weight prep + X split (interleaved) ----------------
__global__ void init_kernel(const float* __restrict__ x,
                            const float* __restrict__ W1s, const float* __restrict__ W1n,
                            const float* __restrict__ W2s, const float* __restrict__ W2n) {
    int idx = blockIdx.x * blockDim.x + threadIdx.x;
    if (idx < NN) g_cnt[idx] = 0;
    if (idx < 2 * 128 * 256) {
        int layer = idx >> 15;
        int e = idx & 32767;
        int j = e >> 8;
        int k = e & 255;
        const float* Ws = layer ? W2s : W1s;
        const float* Wn = layer ? W2n : W1n;
        float v = (k < 128) ? Ws[k * 128 + j] : Wn[(k - 128) * 128 + j];
        uint16_t hi = bf_hi(v);
        uint16_t lo = bf_hi(v - bf_f((uint32_t)hi));
        if (layer) { g_WT2h[e] = hi; g_WT2l[e] = lo; }
        else       { g_WT1h[e] = hi; g_WT1l[e] = lo; }
    }
    if (idx < NN * D / 4) {
        float4 v = ((const float4*)x)[idx];
        uint16_t h0 = bf_hi(v.x), h1 = bf_hi(v.y), h2 = bf_hi(v.z), h3 = bf_hi(v.w);
        uint16_t l0 = bf_hi(v.x - bf_f(h0)), l1 = bf_hi(v.y - bf_f(h1));
        uint16_t l2 = bf_hi(v.z - bf_f(h2)), l3 = bf_hi(v.w - bf_f(h3));
        uint4 w;
        w.x = (uint32_t)h0 | ((uint32_t)h1 << 16);   // hi01
        w.y = (uint32_t)h2 | ((uint32_t)h3 << 16);   // hi23
        w.z = (uint32_t)l0 | ((uint32_t)l1 << 16);   // lo01
        w.w = (uint32_t)l2 | ((uint32_t)l3 << 16);   // lo23
        ((uint4*)g_Xp)[idx] = w;
    }
}

// ---------------- bucket fill: one atomic per edge, no scan ----------------
__global__ void fill_kernel(const int* __restrict__ src, const int* __restrict__ dst) {
    int e = blockIdx.x * blockDim.x + threadIdx.x;
    if (e < EE) {
        int d = dst[e];
        int pos = atomicAdd(&g_cnt[d], 1);
        if (pos < CAP) g_colp[(size_t)d * CAP + pos] = src[e];
    }
}

// ---------------- fused agg+GEMM kernel ----------------
// 384 threads: warps 0-7 = MMA (R6 pipeline), warps 8-11 = aggregation.
#define PITCHB 144                          // bytes per smem row (72 bf16)
#define MATB   (128 * PITCHB)               // 18432
#define STAGEB (4 * MATB)                   // 73728 per stage (Ah, Al, Bh, Bl)
#define MEANOFF (2 * STAGEB)                // mean tiles: [H_c2][L_c2][H_c3][L_c3]
#define SM_BYTES (2 * STAGEB + 4 * MATB)    // 221184

__device__ __forceinline__ void mma_bf16(float* c, const uint32_t* a, uint32_t b0, uint32_t b1) {
    asm volatile("mma.sync.aligned.m16n8k16.row.col.f32.bf16.bf16.f32 "
                 "{%0,%1,%2,%3}, {%4,%5,%6,%7}, {%8,%9}, {%0,%1,%2,%3};"
                 : "+f"(c[0]), "+f"(c[1]), "+f"(c[2]), "+f"(c[3])
                 : "r"(a[0]), "r"(a[1]), "r"(a[2]), "r"(a[3]), "r"(b0), "r"(b1));
}
__device__ __forceinline__ void ldsm_x4(uint32_t* r, uint32_t addr) {
    asm volatile("ldmatrix.sync.aligned.m8n8.x4.shared.b16 {%0,%1,%2,%3}, [%4];"
                 : "=r"(r[0]), "=r"(r[1]), "=r"(r[2]), "=r"(r[3]) : "r"(addr));
}
__device__ __forceinline__ void cp16(uint32_t dst, const void* src, uint32_t sz) {
    asm volatile("cp.async.cg.shared.global [%0], [%1], 16, %2;" :: "r"(dst), "l"(src), "r"(sz));
}
__device__ __forceinline__ void cp8(uint32_t dst, const void* src, uint32_t sz) {
    asm volatile("cp.async.ca.shared.global [%0], [%1], 8, %2;" :: "r"(dst), "l"(src), "r"(sz));
}
__device__ __forceinline__ uint32_t smem_u32(const void* p) {
    uint32_t a;
    asm("{ .reg .u64 t; cvta.to.shared.u64 t, %1; cvt.u32.u64 %0, t; }" : "=r"(a) : "l"(p));
    return a;
}
#define BAR_MMA() asm volatile("bar.sync 0, 256;" ::: "memory")
#define BAR_ALL() asm volatile("bar.sync 1, 384;" ::: "memory")
#define FULLMASK 0xFFFFFFFFu

template <bool RELU, bool SPLIT>
__global__ void __launch_bounds__(384, 1)
fused_layer_kernel(const uint2* __restrict__ Sp,   // interleaved hi/lo source matrix
                   const uint16_t* __restrict__ WTh, const uint16_t* __restrict__ WTl,
                   const float* __restrict__ bias,
                   float* __restrict__ outF, uint2* __restrict__ outP) {
    extern __shared__ char sm[];
    const uint32_t sbase = smem_u32(sm);
    const int tid  = threadIdx.x;
    const int wid  = tid >> 5;
    const int lane = tid & 31;
    const int row0 = blockIdx.x * 128;

    if (wid >= 8) {
        // ============ aggregation warps: 4 warps, 32 rows each, deep-pipelined ============
        const int aw = wid - 8;
        const uint4* Xp4 = (const uint4*)Sp;
        const uint32_t tileBase = (MEANOFF) + ((lane < 16) ? 0 : 2 * MATB);
        const int tl = lane & 15;

        // preload this warp's 32 row degree counts (coalesced)
        int gr_l = row0 + aw * 32 + lane;
        int cnt_l = 0;
        if (gr_l < NN) cnt_l = min(g_cnt[gr_l], CAP);

        for (int p = 0; p < 32; p++) {
            int r  = aw * 32 + p;
            int gr = row0 + r;
            int cnt = __shfl_sync(FULLMASK, cnt_l, p);
            float4 acc = make_float4(0.f, 0.f, 0.f, 0.f);
            if (cnt > 0) {
                const int* cp = g_colp + (size_t)gr * CAP;
                for (int base = 0; base < cnt; base += 32) {
                    int m = min(32, cnt - base);
                    int eidx = cp[base + ((lane < m) ? lane : 0)];
                    uint4 bufA[16], bufB[16];
                    // phase 1: launch first 16 gathers back-to-back
#pragma unroll
                    for (int j = 0; j < 16; j++) {
                        if (j < m) {
                            int s = __shfl_sync(FULLMASK, eidx, j);
                            bufA[j] = Xp4[(size_t)s * 32 + lane];
                        }
                    }
                    // phase 2: refill second half while consuming first
#pragma unroll
                    for (int j = 0; j < 16; j++) {
                        if (16 + j < m) {
                            int s = __shfl_sync(FULLMASK, eidx, 16 + j);
                            bufB[j] = Xp4[(size_t)s * 32 + lane];
                        }
                        if (j < m) {
                            uint4 v = bufA[j];
                            acc.x += bf_f(v.x & 0xFFFF) + bf_f(v.z & 0xFFFF);
                            acc.y += bf_f(v.x >> 16)    + bf_f(v.z >> 16);
                            acc.z += bf_f(v.y & 0xFFFF) + bf_f(v.w & 0xFFFF);
                            acc.w += bf_f(v.y >> 16)    + bf_f(v.w >> 16);
                        }
                    }
                    // phase 3: consume second half
#pragma unroll
                    for (int j = 0; j < 16; j++) {
                        if (16 + j < m) {
                            uint4 v = bufB[j];
                            acc.x += bf_f(v.x & 0xFFFF) + bf_f(v.z & 0xFFFF);
                            acc.y += bf_f(v.x >> 16)    + bf_f(v.z >> 16);
                            acc.z += bf_f(v.y & 0xFFFF) + bf_f(v.w & 0xFFFF);
                            acc.w += bf_f(v.y >> 16)    + bf_f(v.w >> 16);
                        }
                    }
                }
                float inv = 1.0f / (float)cnt;
                acc.x *= inv; acc.y *= inv; acc.z *= inv; acc.w *= inv;
            }
            // split to hi/lo bf16 and store into mean smem tiles
            uint16_t h0 = bf_hi(acc.x), h1 = bf_hi(acc.y), h2 = bf_hi(acc.z), h3 = bf_hi(acc.w);
            uint16_t l0 = bf_hi(acc.x - bf_f(h0)), l1 = bf_hi(acc.y - bf_f(h1));
            uint16_t l2 = bf_hi(acc.z - bf_f(h2)), l3 = bf_hi(acc.w - bf_f(h3));
            uint2 hw, lw;
            hw.x = (uint32_t)h0 | ((uint32_t)h1 << 16);
            hw.y = (uint32_t)h2 | ((uint32_t)h3 << 16);
            lw.x = (uint32_t)l0 | ((uint32_t)l1 << 16);
            lw.y = (uint32_t)l2 | ((uint32_t)l3 << 16);
            *(uint2*)(sm + tileBase + r * PITCHB + tl * 8) = hw;
            *(uint2*)(sm + tileBase + MATB + r * PITCHB + tl * 8) = lw;
        }
        BAR_ALL();   // mean tiles ready
        return;
    }

    // ============ MMA warps (8 warps, R6 pipeline) ============
    const int grp = lane >> 2;
    const int qp  = lane & 3;
    const int wm  = wid >> 1;    // 0..3 -> rows wm*32
    const int wn  = wid & 1;     // 0..1 -> cols wn*64

    const uint32_t arow_off = (uint32_t)((lane & 15) * PITCHB + ((lane >> 4) << 4));
    const uint32_t brow_off = (uint32_t)((((lane >> 4) << 3) + (lane & 7)) * PITCHB + (((lane >> 3) & 1) << 4));

    float acc[2][8][4];
#pragma unroll
    for (int mf = 0; mf < 2; mf++)
#pragma unroll
        for (int nf = 0; nf < 8; nf++)
#pragma unroll
            for (int q = 0; q < 4; q++) acc[mf][nf][q] = 0.f;

    auto issue_chunk = [&](int c, uint32_t bufoff) {
        const int k0 = c * 64;
        if (c < 2) {
            // A from interleaved Sp: per (mat, r, c16): two 8B cp.async
            const char* srcb = (const char*)Sp;
#pragma unroll
            for (int i = 0; i < 8; i++) {
                int idx = tid + i * 256;
                int mat = idx >> 10;
                int e   = idx & 1023;
                int r   = e >> 3;
                int c16 = e & 7;
                int gr  = row0 + r;
                int grs = (gr < NN) ? gr : 0;
                int L0  = c * 16 + 2 * c16;   // lane-group of first 4 cols
                const char* s1 = srcb + (size_t)grs * 512 + L0 * 16 + (mat ? 8 : 0);
                uint32_t dst = sbase + bufoff + (mat ? MATB : 0) + r * PITCHB + c16 * 16;
                uint32_t sz = (gr < NN) ? 8u : 0u;
                cp8(dst, s1, sz);
                cp8(dst + 8, s1 + 16, sz);
            }
        }
#pragma unroll
        for (int i = 0; i < 8; i++) {
            int idx = tid + i * 256;
            int mat = idx >> 10;
            int e   = idx & 1023;
            int j   = e >> 3;
            int c16 = e & 7;
            const uint16_t* srcp = (mat ? WTl : WTh) + (size_t)j * 256 + k0 + c16 * 8;
            uint32_t dst = sbase + bufoff + (mat ? 3 * MATB : 2 * MATB) + j * PITCHB + c16 * 16;
            cp16(dst, srcp, 16u);
        }
    };

    issue_chunk(0, 0);
    asm volatile("cp.async.commit_group;" ::: "memory");

#pragma unroll
    for (int chunk = 0; chunk < 4; chunk++) {
        const uint32_t bufoff = (chunk & 1) * STAGEB;
        if (chunk < 3) {
            issue_chunk(chunk + 1, ((chunk + 1) & 1) * STAGEB);
            asm volatile("cp.async.commit_group;" ::: "memory");
            asm volatile("cp.async.wait_group 1;" ::: "memory");
        } else {
            asm volatile("cp.async.wait_group 0;" ::: "memory");
        }
        BAR_MMA();
        if (chunk == 2) BAR_ALL();   // wait for agg warps' mean tiles

        uint32_t aBaseH, aBaseL;
        if (chunk < 2) {
            aBaseH = sbase + bufoff + (wm * 32) * PITCHB + arow_off;
            aBaseL = aBaseH + MATB;
        } else {
            aBaseH = sbase + MEANOFF + (chunk - 2) * 2 * MATB + (wm * 32) * PITCHB + arow_off;
            aBaseL = aBaseH + MATB;
        }
        const uint32_t bBaseH = sbase + bufoff + 2 * MATB + (wn * 64) * PITCHB + brow_off;
        const uint32_t bBaseL = bBaseH + MATB;

#pragma unroll
        for (int ks = 0; ks < 64; ks += 16) {
            uint32_t ah[2][4], al[2][4];
#pragma unroll
            for (int mf = 0; mf < 2; mf++) {
                ldsm_x4(ah[mf], aBaseH + mf * (16 * PITCHB) + ks * 2);
                ldsm_x4(al[mf], aBaseL + mf * (16 * PITCHB) + ks * 2);
            }
#pragma unroll
            for (int np = 0; np < 4; np++) {
                uint32_t bh[4], bl[4];
                ldsm_x4(bh, bBaseH + np * (16 * PITCHB) + ks * 2);
                ldsm_x4(bl, bBaseL + np * (16 * PITCHB) + ks * 2);
                int nf0 = np * 2, nf1 = np * 2 + 1;
                mma_bf16(acc[0][nf0], ah[0], bh[0], bh[1]);
                mma_bf16(acc[1][nf0], ah[1], bh[0], bh[1]);
                mma_bf16(acc[0][nf1], ah[0], bh[2], bh[3]);
                mma_bf16(acc[1][nf1], ah[1], bh[2], bh[3]);
                mma_bf16(acc[0][nf0], al[0], bh[0], bh[1]);
                mma_bf16(acc[1][nf0], al[1], bh[0], bh[1]);
                mma_bf16(acc[0][nf1], al[0], bh[2], bh[3]);
                mma_bf16(acc[1][nf1], al[1], bh[2], bh[3]);
                mma_bf16(acc[0][nf0], ah[0], bl[0], bl[1]);
                mma_bf16(acc[1][nf0], ah[1], bl[0], bl[1]);
                mma_bf16(acc[0][nf1], ah[0], bl[2], bl[3]);
                mma_bf16(acc[1][nf1], ah[1], bl[2], bl[3]);
            }
        }
        BAR_MMA();
    }

    // epilogue
#pragma unroll
    for (int mf = 0; mf < 2; mf++) {
#pragma unroll
        for (int nf = 0; nf < 8; nf++) {
            int c = wn * 64 + nf * 8 + qp * 2;
            int r = row0 + wm * 32 + mf * 16 + grp;
            float bx = bias[c], by = bias[c + 1];
            float v00 = acc[mf][nf][0] + bx, v01 = acc[mf][nf][1] + by;
            float v10 = acc[mf][nf][2] + bx, v11 = acc[mf][nf][3] + by;
            if (RELU) {
                v00 = fmaxf(v00, 0.f); v01 = fmaxf(v01, 0.f);
                v10 = fmaxf(v10, 0.f); v11 = fmaxf(v11, 0.f);
            }
#pragma unroll
            for (int half = 0; half < 2; half++) {
                int rr = r + half * 8;
                if (rr >= NN) continue;
                float va = half ? v10 : v00;
                float vb = half ? v11 : v01;
                if (SPLIT) {
                    uint16_t ha = bf_hi(va), hb = bf_hi(vb);
                    uint16_t la = bf_hi(va - bf_f(ha)), lb = bf_hi(vb - bf_f(hb));
                    // interleaved layout: node*512 + (c/4)*16 + ((c/2)&1)*4 (hi), +8 (lo)
                    char* bp = (char*)outP + (size_t)rr * 512 + (c >> 2) * 16 + ((c >> 1) & 1) * 4;
                    *(uint32_t*)bp       = (uint32_t)ha | ((uint32_t)hb << 16);
                    *(uint32_t*)(bp + 8) = (uint32_t)la | ((uint32_t)lb << 16);
                } else {
                    *(float2*)(outF + (size_t)rr * D + c) = make_float2(va, vb);
                }
            }
        }
    }
}

// ---------------- launch ----------------
extern "C" void kernel_launch(void* const* d_in, const int* in_sizes, int n_in,
                              void* d_out, int out_size) {
    const float* x   = (const float*)d_in[0];
    const float* W1s = (const float*)d_in[1];
    const float* W1n = (const float*)d_in[2];
    const float* b1  = (const float*)d_in[3];
    const float* W2s = (const float*)d_in[4];
    const float* W2n = (const float*)d_in[5];
    const float* b2  = (const float*)d_in[6];
    const int*   src = (const int*)d_in[7];
    const int*   dst = (const int*)d_in[8];
    float* out = (float*)d_out;

    uint2 *xp, *hp;
    uint16_t *wt1h, *wt1l, *wt2h, *wt2l;
    cudaGetSymbolAddress((void**)&xp, g_Xp);
    cudaGetSymbolAddress((void**)&hp, g_hp);
    cudaGetSymbolAddress((void**)&wt1h, g_WT1h);
    cudaGetSymbolAddress((void**)&wt1l, g_WT1l);
    cudaGetSymbolAddress((void**)&wt2h, g_WT2h);
    cudaGetSymbolAddress((void**)&wt2l, g_WT2l);

    cudaFuncSetAttribute(fused_layer_kernel<true, true>,   cudaFuncAttributeMaxDynamicSharedMemorySize, SM_BYTES);
    cudaFuncSetAttribute(fused_layer_kernel<false, false>, cudaFuncAttributeMaxDynamicSharedMemorySize, SM_BYTES);

    const int gemmGrid = (NN + 127) / 128;   // 782

    init_kernel<<<(NN * D / 4 + 255) / 256, 256>>>(x, W1s, W1n, W2s, W2n);
    fill_kernel<<<(EE + 255) / 256, 256>>>(src, dst);

    // layer 1: agg(x) || gemm -> h (interleaved hi/lo)
    fused_layer_kernel<true, true><<<gemmGrid, 384, SM_BYTES>>>(xp, wt1h, wt1l, b1, nullptr, hp);

    // layer 2: agg(h) || gemm -> out (fp32)
    fused_layer_kernel<false, false><<<gemmGrid, 384, SM_BYTES>>>(hp, wt2h, wt2l, b2, out, nullptr);
}

// round 14
// speedup vs baseline: 6.3821x; 6.3821x over previous
#include <cuda_runtime.h>
#include <cuda_bf16.h>
#include <cstdint>

#define NN 100000
#define EE 1600000
#define D  128
#define CAP 128

// ---------------- device scratch (no allocations allowed) ----------------
__device__ int      g_cnt[NN];
__device__ int      g_colp[(size_t)NN * CAP];
__device__ uint16_t g_Xh[(size_t)NN * D];   // bf16 bits, hi part of x
__device__ uint16_t g_Xl[(size_t)NN * D];
__device__ uint16_t g_hh[(size_t)NN * D];   // hidden layer hi/lo
__device__ uint16_t g_hl[(size_t)NN * D];
__device__ uint16_t g_mh[(size_t)NN * D];   // mean hi/lo
__device__ uint16_t g_ml[(size_t)NN * D];
// W transposed+split: [j=0..127][k=0..255] bf16, k<128 -> Wself[k][j], k>=128 -> Wneigh[k-128][j]
__device__ uint16_t g_WT1h[128 * 256];
__device__ uint16_t g_WT1l[128 * 256];
__device__ uint16_t g_WT2h[128 * 256];
__device__ uint16_t g_WT2l[128 * 256];

__device__ __forceinline__ uint16_t bf_hi(float v) {
    return __bfloat16_as_ushort(__float2bfloat16(v));
}
__device__ __forceinline__ float bf_f(uint16_t u) {
    return __uint_as_float((uint32_t)u << 16);
}

// ---------------- tiny zero kernel (must precede fill's atomics) ----------------
__global__ void zero_cnt_kernel() {
    int i = blockIdx.x * blockDim.x + threadIdx.x;
    if (i < NN) g_cnt[i] = 0;
}

// ---------------- fused: bucket fill + weight prep + X split (one launch) ----------------
__global__ void prep_fill_kernel(const float* __restrict__ x,
                                 const float* __restrict__ W1s, const float* __restrict__ W1n,
                                 const float* __restrict__ W2s, const float* __restrict__ W2n,
                                 const int* __restrict__ src, const int* __restrict__ dst) {
    int idx = blockIdx.x * blockDim.x + threadIdx.x;   // 3.2M threads
    if (idx < EE) {
        int d = dst[idx];
        int pos = atomicAdd(&g_cnt[d], 1);
        if (pos < CAP) g_colp[(size_t)d * CAP + pos] = src[idx];
    }
    if (idx < 2 * 128 * 256) {
        int layer = idx >> 15;
        int e = idx & 32767;
        int j = e >> 8;
        int k = e & 255;
        const float* Ws = layer ? W2s : W1s;
        const float* Wn = layer ? W2n : W1n;
        float v = (k < 128) ? Ws[k * 128 + j] : Wn[(k - 128) * 128 + j];
        uint16_t hi = bf_hi(v);
        uint16_t lo = bf_hi(v - bf_f(hi));
        if (layer) { g_WT2h[e] = hi; g_WT2l[e] = lo; }
        else       { g_WT1h[e] = hi; g_WT1l[e] = lo; }
    }
    if (idx < NN * D / 4) {
        float4 v = ((const float4*)x)[idx];
        uint16_t h0 = bf_hi(v.x), h1 = bf_hi(v.y), h2 = bf_hi(v.z), h3 = bf_hi(v.w);
        uint16_t l0 = bf_hi(v.x - bf_f(h0)), l1 = bf_hi(v.y - bf_f(h1));
        uint16_t l2 = bf_hi(v.z - bf_f(h2)), l3 = bf_hi(v.w - bf_f(h3));
        uint2 hw, lw;
        hw.x = (uint32_t)h0 | ((uint32_t)h1 << 16);
        hw.y = (uint32_t)h2 | ((uint32_t)h3 << 16);
        lw.x = (uint32_t)l0 | ((uint32_t)l1 << 16);
        lw.y = (uint32_t)l2 | ((uint32_t)l3 << 16);
        *(uint2*)(g_Xh + (size_t)idx * 4) = hw;
        *(uint2*)(g_Xl + (size_t)idx * 4) = lw;
    }
}

// ---------------- aggregation: warp per dst node, bf16 hi/lo out ----------------
__device__ __forceinline__ void write_mean(int w, int lane, float4 acc, int cnt) {
    float inv = (cnt > 0) ? 1.0f / (float)cnt : 0.0f;
    acc.x *= inv; acc.y *= inv; acc.z *= inv; acc.w *= inv;
    uint16_t h0 = bf_hi(acc.x), h1 = bf_hi(acc.y), h2 = bf_hi(acc.z), h3 = bf_hi(acc.w);
    uint16_t l0 = bf_hi(acc.x - bf_f(h0)), l1 = bf_hi(acc.y - bf_f(h1));
    uint16_t l2 = bf_hi(acc.z - bf_f(h2)), l3 = bf_hi(acc.w - bf_f(h3));
    uint2 hw, lw;
    hw.x = (uint32_t)h0 | ((uint32_t)h1 << 16);
    hw.y = (uint32_t)h2 | ((uint32_t)h3 << 16);
    lw.x = (uint32_t)l0 | ((uint32_t)l1 << 16);
    lw.y = (uint32_t)l2 | ((uint32_t)l3 << 16);
    *(uint2*)(g_mh + (size_t)w * D + lane * 4) = hw;
    *(uint2*)(g_ml + (size_t)w * D + lane * 4) = lw;
}

__global__ void agg_f32_kernel(const float* __restrict__ x) {
    int gt   = blockIdx.x * blockDim.x + threadIdx.x;
    int w    = gt >> 5;
    int lane = gt & 31;
    if (w >= NN) return;
    int cnt = min(g_cnt[w], CAP);
    const int* cp = g_colp + (size_t)w * CAP;
    const float4* x4 = (const float4*)x;
    float4 acc = make_float4(0.f, 0.f, 0.f, 0.f);
    for (int e = 0; e < cnt; e++) {
        int s = cp[e];
        float4 v = x4[(size_t)s * 32 + lane];
        acc.x += v.x; acc.y += v.y; acc.z += v.z; acc.w += v.w;
    }
    write_mean(w, lane, acc, cnt);
}

__global__ void agg_bf_kernel() {
    int gt   = blockIdx.x * blockDim.x + threadIdx.x;
    int w    = gt >> 5;
    int lane = gt & 31;
    if (w >= NN) return;
    int cnt = min(g_cnt[w], CAP);
    const int* cp = g_colp + (size_t)w * CAP;
    float4 acc = make_float4(0.f, 0.f, 0.f, 0.f);
    for (int e = 0; e < cnt; e++) {
        int s = cp[e];
        uint2 hv = *(const uint2*)(g_hh + (size_t)s * D + lane * 4);
        uint2 lv = *(const uint2*)(g_hl + (size_t)s * D + lane * 4);
        acc.x += bf_f((uint16_t)(hv.x & 0xFFFF)) + bf_f((uint16_t)(lv.x & 0xFFFF));
        acc.y += bf_f((uint16_t)(hv.x >> 16))    + bf_f((uint16_t)(lv.x >> 16));
        acc.z += bf_f((uint16_t)(hv.y & 0xFFFF)) + bf_f((uint16_t)(lv.y & 0xFFFF));
        acc.w += bf_f((uint16_t)(hv.y >> 16))    + bf_f((uint16_t)(lv.y >> 16));
    }
    write_mean(w, lane, acc, cnt);
}

// ---------------- async-pipelined HMMA GEMM (R6, unchanged) ----------------
// CTA 128x128, 256 threads, 8 warps (4m x 2n), warp tile 32x64, K=256 in 4 chunks of 64,
// double-buffered cp.async staging: Ah/Al/Bh/Bl per chunk, pitch 144 B.
#define PITCHB 144                         // bytes per smem row (72 bf16)
#define MATB   (128 * PITCHB)              // 18432 bytes per matrix tile
#define STAGEB (4 * MATB)                  // 73728 bytes per stage
#define SM_BYTES (2 * STAGEB)              // 147456

__device__ __forceinline__ void mma_bf16(float* c, const uint32_t* a, uint32_t b0, uint32_t b1) {
    asm volatile("mma.sync.aligned.m16n8k16.row.col.f32.bf16.bf16.f32 "
                 "{%0,%1,%2,%3}, {%4,%5,%6,%7}, {%8,%9}, {%0,%1,%2,%3};"
                 : "+f"(c[0]), "+f"(c[1]), "+f"(c[2]), "+f"(c[3])
                 : "r"(a[0]), "r"(a[1]), "r"(a[2]), "r"(a[3]), "r"(b0), "r"(b1));
}
__device__ __forceinline__ void ldsm_x4(uint32_t* r, uint32_t addr) {
    asm volatile("ldmatrix.sync.aligned.m8n8.x4.shared.b16 {%0,%1,%2,%3}, [%4];"
                 : "=r"(r[0]), "=r"(r[1]), "=r"(r[2]), "=r"(r[3]) : "r"(addr));
}
__device__ __forceinline__ void cp16(uint32_t dst, const void* src, uint32_t sz) {
    asm volatile("cp.async.cg.shared.global [%0], [%1], 16, %2;" :: "r"(dst), "l"(src), "r"(sz));
}
__device__ __forceinline__ uint32_t smem_u32(const void* p) {
    uint32_t a;
    asm("{ .reg .u64 t; cvta.to.shared.u64 t, %1; cvt.u32.u64 %0, t; }" : "=r"(a) : "l"(p));
    return a;
}

template <bool RELU, bool SPLIT>
__global__ void __launch_bounds__(256, 1)
gemm_async_kernel(const uint16_t* __restrict__ Sh, const uint16_t* __restrict__ Sl,
                  const uint16_t* __restrict__ WTh, const uint16_t* __restrict__ WTl,
                  const float* __restrict__ bias,
                  float* __restrict__ outF, uint16_t* __restrict__ outH, uint16_t* __restrict__ outL) {
    extern __shared__ char sm[];
    const uint32_t sbase = smem_u32(sm);
    const int tid  = threadIdx.x;
    const int wid  = tid >> 5;
    const int lane = tid & 31;
    const int grp  = lane >> 2;
    const int qp   = lane & 3;
    const int wm   = wid >> 1;    // 0..3 -> rows wm*32
    const int wn   = wid & 1;     // 0..1 -> cols wn*64
    const int row0 = blockIdx.x * 128;

    const uint32_t arow_off = (uint32_t)((lane & 15) * PITCHB + ((lane >> 4) << 4));
    const uint32_t brow_off = (uint32_t)((((lane >> 4) << 3) + (lane & 7)) * PITCHB + (((lane >> 3) & 1) << 4));

    float acc[2][8][4];
#pragma unroll
    for (int mf = 0; mf < 2; mf++)
#pragma unroll
        for (int nf = 0; nf < 8; nf++)
#pragma unroll
            for (int q = 0; q < 4; q++) acc[mf][nf][q] = 0.f;

    auto issue_chunk = [&](int c, uint32_t bufoff) {
        const uint16_t* Ah_g = (c < 2) ? Sh : g_mh;
        const uint16_t* Al_g = (c < 2) ? Sl : g_ml;
        const int kc = (c & 1) * 64;
        const int k0 = c * 64;
#pragma unroll
        for (int i = 0; i < 8; i++) {
            int idx = tid + i * 256;
            int mat = idx >> 10;
            int e   = idx & 1023;
            int r   = e >> 3;
            int c16 = e & 7;
            int gr  = row0 + r;
            int grs = (gr < NN) ? gr : 0;
            const uint16_t* srcp = (mat ? Al_g : Ah_g) + (size_t)grs * D + kc + c16 * 8;
            uint32_t dst = sbase + bufoff + (mat ? MATB : 0) + r * PITCHB + c16 * 16;
            cp16(dst, srcp, (gr < NN) ? 16u : 0u);
        }
#pragma unroll
        for (int i = 0; i < 8; i++) {
            int idx = tid + i * 256;
            int mat = idx >> 10;
            int e   = idx & 1023;
            int j   = e >> 3;
            int c16 = e & 7;
            const uint16_t* srcp = (mat ? WTl : WTh) + (size_t)j * 256 + k0 + c16 * 8;
            uint32_t dst = sbase + bufoff + (mat ? 3 * MATB : 2 * MATB) + j * PITCHB + c16 * 16;
            cp16(dst, srcp, 16u);
        }
    };

    issue_chunk(0, 0);
    asm volatile("cp.async.commit_group;" ::: "memory");

#pragma unroll
    for (int chunk = 0; chunk < 4; chunk++) {
        const uint32_t bufoff = (chunk & 1) * STAGEB;
        if (chunk < 3) {
            issue_chunk(chunk + 1, ((chunk + 1) & 1) * STAGEB);
            asm volatile("cp.async.commit_group;" ::: "memory");
            asm volatile("cp.async.wait_group 1;" ::: "memory");
        } else {
            asm volatile("cp.async.wait_group 0;" ::: "memory");
        }
        __syncthreads();

        const uint32_t aBaseH = sbase + bufoff + (wm * 32) * PITCHB + arow_off;
        const uint32_t aBaseL = aBaseH + MATB;
        const uint32_t bBaseH = sbase + bufoff + 2 * MATB + (wn * 64) * PITCHB + brow_off;
        const uint32_t bBaseL = bBaseH + MATB;

#pragma unroll
        for (int ks = 0; ks < 64; ks += 16) {
            uint32_t ah[2][4], al[2][4];
#pragma unroll
            for (int mf = 0; mf < 2; mf++) {
                ldsm_x4(ah[mf], aBaseH + mf * (16 * PITCHB) + ks * 2);
                ldsm_x4(al[mf], aBaseL + mf * (16 * PITCHB) + ks * 2);
            }
#pragma unroll
            for (int np = 0; np < 4; np++) {
                uint32_t bh[4], bl[4];
                ldsm_x4(bh, bBaseH + np * (16 * PITCHB) + ks * 2);
                ldsm_x4(bl, bBaseL + np * (16 * PITCHB) + ks * 2);
                int nf0 = np * 2, nf1 = np * 2 + 1;
                mma_bf16(acc[0][nf0], ah[0], bh[0], bh[1]);
                mma_bf16(acc[1][nf0], ah[1], bh[0], bh[1]);
                mma_bf16(acc[0][nf1], ah[0], bh[2], bh[3]);
                mma_bf16(acc[1][nf1], ah[1], bh[2], bh[3]);
                mma_bf16(acc[0][nf0], al[0], bh[0], bh[1]);
                mma_bf16(acc[1][nf0], al[1], bh[0], bh[1]);
                mma_bf16(acc[0][nf1], al[0], bh[2], bh[3]);
                mma_bf16(acc[1][nf1], al[1], bh[2], bh[3]);
                mma_bf16(acc[0][nf0], ah[0], bl[0], bl[1]);
                mma_bf16(acc[1][nf0], ah[1], bl[0], bl[1]);
                mma_bf16(acc[0][nf1], ah[0], bl[2], bl[3]);
                mma_bf16(acc[1][nf1], ah[1], bl[2], bl[3]);
            }
        }
        __syncthreads();
    }

    // epilogue
#pragma unroll
    for (int mf = 0; mf < 2; mf++) {
#pragma unroll
        for (int nf = 0; nf < 8; nf++) {
            int c = wn * 64 + nf * 8 + qp * 2;
            int r = row0 + wm * 32 + mf * 16 + grp;
            float bx = bias[c], by = bias[c + 1];
            float v00 = acc[mf][nf][0] + bx, v01 = acc[mf][nf][1] + by;
            float v10 = acc[mf][nf][2] + bx, v11 = acc[mf][nf][3] + by;
            if (RELU) {
                v00 = fmaxf(v00, 0.f); v01 = fmaxf(v01, 0.f);
                v10 = fmaxf(v10, 0.f); v11 = fmaxf(v11, 0.f);
            }
            if (SPLIT) {
                uint16_t h00 = bf_hi(v00), h01 = bf_hi(v01), h10 = bf_hi(v10), h11 = bf_hi(v11);
                uint16_t l00 = bf_hi(v00 - bf_f(h00)), l01 = bf_hi(v01 - bf_f(h01));
                uint16_t l10 = bf_hi(v10 - bf_f(h10)), l11 = bf_hi(v11 - bf_f(h11));
                if (r < NN) {
                    *(uint32_t*)(outH + (size_t)r * D + c) = (uint32_t)h00 | ((uint32_t)h01 << 16);
                    *(uint32_t*)(outL + (size_t)r * D + c) = (uint32_t)l00 | ((uint32_t)l01 << 16);
                }
                if (r + 8 < NN) {
                    *(uint32_t*)(outH + (size_t)(r + 8) * D + c) = (uint32_t)h10 | ((uint32_t)h11 << 16);
                    *(uint32_t*)(outL + (size_t)(r + 8) * D + c) = (uint32_t)l10 | ((uint32_t)l11 << 16);
                }
            } else {
                if (r < NN)     { float2 v = make_float2(v00, v01); *(float2*)(outF + (size_t)r * D + c) = v; }
                if (r + 8 < NN) { float2 v = make_float2(v10, v11); *(float2*)(outF + (size_t)(r + 8) * D + c) = v; }
            }
        }
    }
}

// ---------------- launch ----------------
extern "C" void kernel_launch(void* const* d_in, const int* in_sizes, int n_in,
                              void* d_out, int out_size) {
    const float* x   = (const float*)d_in[0];
    const float* W1s = (const float*)d_in[1];
    const float* W1n = (const float*)d_in[2];
    const float* b1  = (const float*)d_in[3];
    const float* W2s = (const float*)d_in[4];
    const float* W2n = (const float*)d_in[5];
    const float* b2  = (const float*)d_in[6];
    const int*   src = (const int*)d_in[7];
    const int*   dst = (const int*)d_in[8];
    float* out = (float*)d_out;

    uint16_t *xh, *xl, *hh, *hl, *wt1h, *wt1l, *wt2h, *wt2l;
    cudaGetSymbolAddress((void**)&xh, g_Xh);
    cudaGetSymbolAddress((void**)&xl, g_Xl);
    cudaGetSymbolAddress((void**)&hh, g_hh);
    cudaGetSymbolAddress((void**)&hl, g_hl);
    cudaGetSymbolAddress((void**)&wt1h, g_WT1h);
    cudaGetSymbolAddress((void**)&wt1l, g_WT1l);
    cudaGetSymbolAddress((void**)&wt2h, g_WT2h);
    cudaGetSymbolAddress((void**)&wt2l, g_WT2l);

    cudaFuncSetAttribute(gemm_async_kernel<true, true>,   cudaFuncAttributeMaxDynamicSharedMemorySize, SM_BYTES);
    cudaFuncSetAttribute(gemm_async_kernel<false, false>, cudaFuncAttributeMaxDynamicSharedMemorySize, SM_BYTES);

    const int gemmGrid = (NN + 127) / 128;   // 782

    // prep: zero counters, then fused fill + weight prep + X split
    zero_cnt_kernel<<<(NN + 255) / 256, 256>>>();
    prep_fill_kernel<<<(NN * D / 4 + 255) / 256, 256>>>(x, W1s, W1n, W2s, W2n, src, dst);

    // layer 1
    agg_f32_kernel<<<(NN * 32 + 255) / 256, 256>>>(x);
    gemm_async_kernel<true, true><<<gemmGrid, 256, SM_BYTES>>>(xh, xl, wt1h, wt1l, b1, nullptr, hh, hl);

    // layer 2
    agg_bf_kernel<<<(NN * 32 + 255) / 256, 256>>>();
    gemm_async_kernel<false, false><<<gemmGrid, 256, SM_BYTES>>>(hh, hl, wt2h, wt2l, b2, out, nullptr, nullptr);
}

// round 15
// speedup vs baseline: 7.3746x; 1.1555x over previous
#include <cuda_runtime.h>
#include <cuda_fp16.h>
#include <cstdint>

#define NN 100000
#define EE 1600000
#define D  128
#define CAP 128

// ---------------- device scratch (no allocations allowed) ----------------
__device__ int      g_cnt[NN];
__device__ int      g_colp[(size_t)NN * CAP];
__device__ uint16_t g_Xh[(size_t)NN * D];   // fp16 bits, hi part of x
__device__ uint16_t g_Xl[(size_t)NN * D];
__device__ uint16_t g_hh[(size_t)NN * D];   // hidden layer hi/lo (fp16)
__device__ uint16_t g_hl[(size_t)NN * D];
__device__ uint16_t g_mh[(size_t)NN * D];   // mean hi/lo (fp16)
__device__ uint16_t g_ml[(size_t)NN * D];
// W transposed, fp16 hi only: [j=0..127][k=0..255], k<128 -> Wself[k][j], k>=128 -> Wneigh[k-128][j]
__device__ uint16_t g_WT1h[128 * 256];
__device__ uint16_t g_WT2h[128 * 256];

__device__ __forceinline__ uint16_t f16_hi(float v) {
    return __half_as_ushort(__float2half_rn(v));
}
__device__ __forceinline__ float f16_f(uint16_t u) {
    return __half2float(__ushort_as_half(u));
}

// ---------------- tiny zero kernel (must precede fill's atomics) ----------------
__global__ void zero_cnt_kernel() {
    int i = blockIdx.x * blockDim.x + threadIdx.x;
    if (i < NN) g_cnt[i] = 0;
}

// ---------------- fused: bucket fill + weight prep + X split (one launch) ----------------
__global__ void prep_fill_kernel(const float* __restrict__ x,
                                 const float* __restrict__ W1s, const float* __restrict__ W1n,
                                 const float* __restrict__ W2s, const float* __restrict__ W2n,
                                 const int* __restrict__ src, const int* __restrict__ dst) {
    int idx = blockIdx.x * blockDim.x + threadIdx.x;   // 3.2M threads
    if (idx < EE) {
        int d = dst[idx];
        int pos = atomicAdd(&g_cnt[d], 1);
        if (pos < CAP) g_colp[(size_t)d * CAP + pos] = src[idx];
    }
    if (idx < 2 * 128 * 256) {
        int layer = idx >> 15;
        int e = idx & 32767;
        int j = e >> 8;
        int k = e & 255;
        const float* Ws = layer ? W2s : W1s;
        const float* Wn = layer ? W2n : W1n;
        float v = (k < 128) ? Ws[k * 128 + j] : Wn[(k - 128) * 128 + j];
        uint16_t hi = f16_hi(v);
        if (layer) g_WT2h[e] = hi;
        else       g_WT1h[e] = hi;
    }
    if (idx < NN * D / 4) {
        float4 v = ((const float4*)x)[idx];
        uint16_t h0 = f16_hi(v.x), h1 = f16_hi(v.y), h2 = f16_hi(v.z), h3 = f16_hi(v.w);
        uint16_t l0 = f16_hi(v.x - f16_f(h0)), l1 = f16_hi(v.y - f16_f(h1));
        uint16_t l2 = f16_hi(v.z - f16_f(h2)), l3 = f16_hi(v.w - f16_f(h3));
        uint2 hw, lw;
        hw.x = (uint32_t)h0 | ((uint32_t)h1 << 16);
        hw.y = (uint32_t)h2 | ((uint32_t)h3 << 16);
        lw.x = (uint32_t)l0 | ((uint32_t)l1 << 16);
        lw.y = (uint32_t)l2 | ((uint32_t)l3 << 16);
        *(uint2*)(g_Xh + (size_t)idx * 4) = hw;
        *(uint2*)(g_Xl + (size_t)idx * 4) = lw;
    }
}

// ---------------- aggregation: warp per dst node, fp16 hi/lo out ----------------
__device__ __forceinline__ void write_mean(int w, int lane, float4 acc, int cnt) {
    float inv = (cnt > 0) ? 1.0f / (float)cnt : 0.0f;
    acc.x *= inv; acc.y *= inv; acc.z *= inv; acc.w *= inv;
    uint16_t h0 = f16_hi(acc.x), h1 = f16_hi(acc.y), h2 = f16_hi(acc.z), h3 = f16_hi(acc.w);
    uint16_t l0 = f16_hi(acc.x - f16_f(h0)), l1 = f16_hi(acc.y - f16_f(h1));
    uint16_t l2 = f16_hi(acc.z - f16_f(h2)), l3 = f16_hi(acc.w - f16_f(h3));
    uint2 hw, lw;
    hw.x = (uint32_t)h0 | ((uint32_t)h1 << 16);
    hw.y = (uint32_t)h2 | ((uint32_t)h3 << 16);
    lw.x = (uint32_t)l0 | ((uint32_t)l1 << 16);
    lw.y = (uint32_t)l2 | ((uint32_t)l3 << 16);
    *(uint2*)(g_mh + (size_t)w * D + lane * 4) = hw;
    *(uint2*)(g_ml + (size_t)w * D + lane * 4) = lw;
}

__global__ void agg_f32_kernel(const float* __restrict__ x) {
    int gt   = blockIdx.x * blockDim.x + threadIdx.x;
    int w    = gt >> 5;
    int lane = gt & 31;
    if (w >= NN) return;
    int cnt = min(g_cnt[w], CAP);
    const int* cp = g_colp + (size_t)w * CAP;
    const float4* x4 = (const float4*)x;
    float4 acc = make_float4(0.f, 0.f, 0.f, 0.f);
    for (int e = 0; e < cnt; e++) {
        int s = cp[e];
        float4 v = x4[(size_t)s * 32 + lane];
        acc.x += v.x; acc.y += v.y; acc.z += v.z; acc.w += v.w;
    }
    write_mean(w, lane, acc, cnt);
}

__global__ void agg_f16_kernel() {
    int gt   = blockIdx.x * blockDim.x + threadIdx.x;
    int w    = gt >> 5;
    int lane = gt & 31;
    if (w >= NN) return;
    int cnt = min(g_cnt[w], CAP);
    const int* cp = g_colp + (size_t)w * CAP;
    float4 acc = make_float4(0.f, 0.f, 0.f, 0.f);
    for (int e = 0; e < cnt; e++) {
        int s = cp[e];
        uint2 hv = *(const uint2*)(g_hh + (size_t)s * D + lane * 4);
        uint2 lv = *(const uint2*)(g_hl + (size_t)s * D + lane * 4);
        float2 fh0 = __half22float2(*(__half2*)&hv.x);
        float2 fh1 = __half22float2(*(__half2*)&hv.y);
        float2 fl0 = __half22float2(*(__half2*)&lv.x);
        float2 fl1 = __half22float2(*(__half2*)&lv.y);
        acc.x += fh0.x + fl0.x;
        acc.y += fh0.y + fl0.y;
        acc.z += fh1.x + fl1.x;
        acc.w += fh1.y + fl1.y;
    }
    write_mean(w, lane, acc, cnt);
}

// ---------------- async-pipelined HMMA GEMM, fp16 2-term (AhBh + AlBh) ----------------
// CTA 128x128, 256 threads, 8 warps (4m x 2n), warp tile 32x64, K=256 in 4 chunks of 64,
// double-buffered cp.async: per stage Ah, Al, Bh (3 tiles). 2 CTAs/SM.
#define PITCHB 144                         // bytes per smem row (72 fp16)
#define MATB   (128 * PITCHB)              // 18432 bytes per matrix tile
#define STAGEB (3 * MATB)                  // 55296 bytes per stage
#define SM_BYTES (2 * STAGEB)              // 110592

__device__ __forceinline__ void mma_f16(float* c, const uint32_t* a, uint32_t b0, uint32_t b1) {
    asm volatile("mma.sync.aligned.m16n8k16.row.col.f32.f16.f16.f32 "
                 "{%0,%1,%2,%3}, {%4,%5,%6,%7}, {%8,%9}, {%0,%1,%2,%3};"
                 : "+f"(c[0]), "+f"(c[1]), "+f"(c[2]), "+f"(c[3])
                 : "r"(a[0]), "r"(a[1]), "r"(a[2]), "r"(a[3]), "r"(b0), "r"(b1));
}
__device__ __forceinline__ void ldsm_x4(uint32_t* r, uint32_t addr) {
    asm volatile("ldmatrix.sync.aligned.m8n8.x4.shared.b16 {%0,%1,%2,%3}, [%4];"
                 : "=r"(r[0]), "=r"(r[1]), "=r"(r[2]), "=r"(r[3]) : "r"(addr));
}
__device__ __forceinline__ void cp16(uint32_t dst, const void* src, uint32_t sz) {
    asm volatile("cp.async.cg.shared.global [%0], [%1], 16, %2;" :: "r"(dst), "l"(src), "r"(sz));
}
__device__ __forceinline__ uint32_t smem_u32(const void* p) {
    uint32_t a;
    asm("{ .reg .u64 t; cvta.to.shared.u64 t, %1; cvt.u32.u64 %0, t; }" : "=r"(a) : "l"(p));
    return a;
}

template <bool RELU, bool SPLIT>
__global__ void __launch_bounds__(256, 2)
gemm_async_kernel(const uint16_t* __restrict__ Sh, const uint16_t* __restrict__ Sl,
                  const uint16_t* __restrict__ WTh,
                  const float* __restrict__ bias,
                  float* __restrict__ outF, uint16_t* __restrict__ outH, uint16_t* __restrict__ outL) {
    extern __shared__ char sm[];
    const uint32_t sbase = smem_u32(sm);
    const int tid  = threadIdx.x;
    const int wid  = tid >> 5;
    const int lane = tid & 31;
    const int grp  = lane >> 2;
    const int qp   = lane & 3;
    const int wm   = wid >> 1;    // 0..3 -> rows wm*32
    const int wn   = wid & 1;     // 0..1 -> cols wn*64
    const int row0 = blockIdx.x * 128;

    const uint32_t arow_off = (uint32_t)((lane & 15) * PITCHB + ((lane >> 4) << 4));
    const uint32_t brow_off = (uint32_t)((((lane >> 4) << 3) + (lane & 7)) * PITCHB + (((lane >> 3) & 1) << 4));

    float acc[2][8][4];
#pragma unroll
    for (int mf = 0; mf < 2; mf++)
#pragma unroll
        for (int nf = 0; nf < 8; nf++)
#pragma unroll
            for (int q = 0; q < 4; q++) acc[mf][nf][q] = 0.f;

    auto issue_chunk = [&](int c, uint32_t bufoff) {
        const uint16_t* Ah_g = (c < 2) ? Sh : g_mh;
        const uint16_t* Al_g = (c < 2) ? Sl : g_ml;
        const int kc = (c & 1) * 64;
        const int k0 = c * 64;
        // A hi+lo: 2048 x 16B, 8 per thread
#pragma unroll
        for (int i = 0; i < 8; i++) {
            int idx = tid + i * 256;
            int mat = idx >> 10;
            int e   = idx & 1023;
            int r   = e >> 3;
            int c16 = e & 7;
            int gr  = row0 + r;
            int grs = (gr < NN) ? gr : 0;
            const uint16_t* srcp = (mat ? Al_g : Ah_g) + (size_t)grs * D + kc + c16 * 8;
            uint32_t dst = sbase + bufoff + (mat ? MATB : 0) + r * PITCHB + c16 * 16;
            cp16(dst, srcp, (gr < NN) ? 16u : 0u);
        }
        // B hi only: 1024 x 16B, 4 per thread
#pragma unroll
        for (int i = 0; i < 4; i++) {
            int idx = tid + i * 256;
            int j   = idx >> 3;
            int c16 = idx & 7;
            const uint16_t* srcp = WTh + (size_t)j * 256 + k0 + c16 * 8;
            uint32_t dst = sbase + bufoff + 2 * MATB + j * PITCHB + c16 * 16;
            cp16(dst, srcp, 16u);
        }
    };

    issue_chunk(0, 0);
    asm volatile("cp.async.commit_group;" ::: "memory");

#pragma unroll
    for (int chunk = 0; chunk < 4; chunk++) {
        const uint32_t bufoff = (chunk & 1) * STAGEB;
        if (chunk < 3) {
            issue_chunk(chunk + 1, ((chunk + 1) & 1) * STAGEB);
            asm volatile("cp.async.commit_group;" ::: "memory");
            asm volatile("cp.async.wait_group 1;" ::: "memory");
        } else {
            asm volatile("cp.async.wait_group 0;" ::: "memory");
        }
        __syncthreads();

        const uint32_t aBaseH = sbase + bufoff + (wm * 32) * PITCHB + arow_off;
        const uint32_t aBaseL = aBaseH + MATB;
        const uint32_t bBaseH = sbase + bufoff + 2 * MATB + (wn * 64) * PITCHB + brow_off;

#pragma unroll
        for (int ks = 0; ks < 64; ks += 16) {
            uint32_t ah[2][4], al[2][4];
#pragma unroll
            for (int mf = 0; mf < 2; mf++) {
                ldsm_x4(ah[mf], aBaseH + mf * (16 * PITCHB) + ks * 2);
                ldsm_x4(al[mf], aBaseL + mf * (16 * PITCHB) + ks * 2);
            }
#pragma unroll
            for (int np = 0; np < 4; np++) {
                uint32_t bh[4];
                ldsm_x4(bh, bBaseH + np * (16 * PITCHB) + ks * 2);
                int nf0 = np * 2, nf1 = np * 2 + 1;
                mma_f16(acc[0][nf0], ah[0], bh[0], bh[1]);
                mma_f16(acc[1][nf0], ah[1], bh[0], bh[1]);
                mma_f16(acc[0][nf1], ah[0], bh[2], bh[3]);
                mma_f16(acc[1][nf1], ah[1], bh[2], bh[3]);
                mma_f16(acc[0][nf0], al[0], bh[0], bh[1]);
                mma_f16(acc[1][nf0], al[1], bh[0], bh[1]);
                mma_f16(acc[0][nf1], al[0], bh[2], bh[3]);
                mma_f16(acc[1][nf1], al[1], bh[2], bh[3]);
            }
        }
        __syncthreads();
    }

    // epilogue
#pragma unroll
    for (int mf = 0; mf < 2; mf++) {
#pragma unroll
        for (int nf = 0; nf < 8; nf++) {
            int c = wn * 64 + nf * 8 + qp * 2;
            int r = row0 + wm * 32 + mf * 16 + grp;
            float bx = bias[c], by = bias[c + 1];
            float v00 = acc[mf][nf][0] + bx, v01 = acc[mf][nf][1] + by;
            float v10 = acc[mf][nf][2] + bx, v11 = acc[mf][nf][3] + by;
            if (RELU) {
                v00 = fmaxf(v00, 0.f); v01 = fmaxf(v01, 0.f);
                v10 = fmaxf(v10, 0.f); v11 = fmaxf(v11, 0.f);
            }
            if (SPLIT) {
                uint16_t h00 = f16_hi(v00), h01 = f16_hi(v01), h10 = f16_hi(v10), h11 = f16_hi(v11);
                uint16_t l00 = f16_hi(v00 - f16_f(h00)), l01 = f16_hi(v01 - f16_f(h01));
                uint16_t l10 = f16_hi(v10 - f16_f(h10)), l11 = f16_hi(v11 - f16_f(h11));
                if (r < NN) {
                    *(uint32_t*)(outH + (size_t)r * D + c) = (uint32_t)h00 | ((uint32_t)h01 << 16);
                    *(uint32_t*)(outL + (size_t)r * D + c) = (uint32_t)l00 | ((uint32_t)l01 << 16);
                }
                if (r + 8 < NN) {
                    *(uint32_t*)(outH + (size_t)(r + 8) * D + c) = (uint32_t)h10 | ((uint32_t)h11 << 16);
                    *(uint32_t*)(outL + (size_t)(r + 8) * D + c) = (uint32_t)l10 | ((uint32_t)l11 << 16);
                }
            } else {
                if (r < NN)     { float2 v = make_float2(v00, v01); *(float2*)(outF + (size_t)r * D + c) = v; }
                if (r + 8 < NN) { float2 v = make_float2(v10, v11); *(float2*)(outF + (size_t)(r + 8) * D + c) = v; }
            }
        }
    }
}

// ---------------- launch ----------------
extern "C" void kernel_launch(void* const* d_in, const int* in_sizes, int n_in,
                              void* d_out, int out_size) {
    const float* x   = (const float*)d_in[0];
    const float* W1s = (const float*)d_in[1];
    const float* W1n = (const float*)d_in[2];
    const float* b1  = (const float*)d_in[3];
    const float* W2s = (const float*)d_in[4];
    const float* W2n = (const float*)d_in[5];
    const float* b2  = (const float*)d_in[6];
    const int*   src = (const int*)d_in[7];
    const int*   dst = (const int*)d_in[8];
    float* out = (float*)d_out;

    uint16_t *xh, *xl, *hh, *hl, *wt1h, *wt2h;
    cudaGetSymbolAddress((void**)&xh, g_Xh);
    cudaGetSymbolAddress((void**)&xl, g_Xl);
    cudaGetSymbolAddress((void**)&hh, g_hh);
    cudaGetSymbolAddress((void**)&hl, g_hl);
    cudaGetSymbolAddress((void**)&wt1h, g_WT1h);
    cudaGetSymbolAddress((void**)&wt2h, g_WT2h);

    cudaFuncSetAttribute(gemm_async_kernel<true, true>,   cudaFuncAttributeMaxDynamicSharedMemorySize, SM_BYTES);
    cudaFuncSetAttribute(gemm_async_kernel<false, false>, cudaFuncAttributeMaxDynamicSharedMemorySize, SM_BYTES);

    const int gemmGrid = (NN + 127) / 128;   // 782

    // prep: zero counters, then fused fill + weight prep + X split
    zero_cnt_kernel<<<(NN + 255) / 256, 256>>>();
    prep_fill_kernel<<<(NN * D / 4 + 255) / 256, 256>>>(x, W1s, W1n, W2s, W2n, src, dst);

    // layer 1
    agg_f32_kernel<<<(NN * 32 + 255) / 256, 256>>>(x);
    gemm_async_kernel<true, true><<<gemmGrid, 256, SM_BYTES>>>(xh, xl, wt1h, b1, nullptr, hh, hl);

    // layer 2
    agg_f16_kernel<<<(NN * 32 + 255) / 256, 256>>>();
    gemm_async_kernel<false, false><<<gemmGrid, 256, SM_BYTES>>>(hh, hl, wt2h, b2, out, nullptr, nullptr);
}